// round 2
// baseline (speedup 1.0000x reference)
#include <cuda_runtime.h>

// Fixed shapes: B=32, T=1024, D=1024 (U unused — all GEMM paths are dead code:
// softmax over a singleton axis makes every attention weight exactly 1.0, so
//   context[b,d] = sum_t values[b,t,d],  aw = 1.0,  cov[b,t] = t).
#define BB 32
#define TT 1024
#define DD 1024
#define D4 256            // float4 per row
#define COLS 8            // float4 columns per block
#define TLANES 32         // t-lanes per column
#define ROWS_PER_LANE (TT / TLANES)   // 32
#define NBLK_D (D4 / COLS)            // 32 d-slices

// Output layout (out_size = B*D + 2*B*T = 98304 floats):
//   [0, B*D)            context
//   [B*D, B*D+B*T)      attention_weights  (all 1.0)
//   [B*D+B*T, end)      coverage           (cov[b,t] = t)

__global__ __launch_bounds__(COLS* TLANES) void fused_kernel(
    const float4* __restrict__ vals, float* __restrict__ out) {
    const int b  = blockIdx.x;            // 0..31
    const int ds = blockIdx.y;            // 0..31 d-slice
    const int tid = threadIdx.x;          // 0..255
    const int col = tid & (COLS - 1);     // 0..7
    const int tl  = tid >> 3;             // 0..31

    __shared__ float4 red[COLS][TLANES];

    // Column base: values[b, 0, (ds*COLS+col)*4]
    const float4* __restrict__ p =
        vals + (size_t)b * TT * D4 + (size_t)ds * COLS + col;

    float x = 0.f, y = 0.f, z = 0.f, w = 0.f;
    // t = tl + 32*i : at any instant the block covers 32 consecutive rows.
#pragma unroll 8
    for (int i = 0; i < ROWS_PER_LANE; ++i) {
        float4 v = p[(size_t)(tl + TLANES * i) * D4];
        x += v.x; y += v.y; z += v.z; w += v.w;
    }
    red[col][tl] = make_float4(x, y, z, w);
    __syncthreads();

    // Deterministic tree reduce over the 32 t-lanes of each column.
#pragma unroll
    for (int s = TLANES / 2; s > 0; s >>= 1) {
        if (tl < s) {
            float4 a = red[col][tl];
            float4 c = red[col][tl + s];
            red[col][tl] = make_float4(a.x + c.x, a.y + c.y, a.z + c.z, a.w + c.w);
        }
        __syncthreads();
    }

    // Context write: 8 float4 per block.
    if (tl == 0) {
        float4* ctx = reinterpret_cast<float4*>(out);
        ctx[(size_t)b * D4 + ds * COLS + col] = red[col][0];
    }

    // aw / cov epilogue: B*T = 32768 floats each = 8192 float4 each.
    // 1024 blocks -> 8 float4 of each per block. Threads 0..7 handle them.
    if (tid < 8) {
        const int blk = b * NBLK_D + ds;       // 0..1023
        const int q = blk * 8 + tid;           // float4 index, 0..8191
        float4* aw4  = reinterpret_cast<float4*>(out + BB * DD);
        float4* cov4 = reinterpret_cast<float4*>(out + BB * DD + BB * TT);
        aw4[q] = make_float4(1.f, 1.f, 1.f, 1.f);
        const int j = q * 4;                   // flat element index into [B,T]
        const int t = j & (TT - 1);            // t = j % 1024 (q*4 aligned)
        cov4[q] = make_float4((float)t, (float)(t + 1), (float)(t + 2), (float)(t + 3));
    }
}

extern "C" void kernel_launch(void* const* d_in, const int* in_sizes, int n_in,
                              void* d_out, int out_size) {
    // Inputs: query, values, W1, b1, W2, b2, W3, b3, V, bV
    const float4* values = (const float4*)d_in[1];
    float* out = (float*)d_out;

    dim3 grid(BB, NBLK_D);
    fused_kernel<<<grid, COLS * TLANES>>>(values, out);
}

// round 3
// speedup vs baseline: 1.0034x; 1.0034x over previous
#include <cuda_runtime.h>

// Fixed shapes: B=32, T=1024, D=1024. All GEMM paths are dead code:
// softmax over a singleton axis => every attention weight == 1.0, so
//   context[b,d] = sum_t values[b,t,d],  aw = 1.0,  cov[b,t] = t.
#define BB 32
#define TT 1024
#define DD 1024
#define D4 256                       // float4 per row
#define NCHUNK 16                    // chunks per batch
#define TC (TT / NCHUNK)             // 64 rows per chunk

// Output layout (98304 floats):
//   [0, B*D)             context
//   [B*D, B*D+B*T)       attention_weights (all 1.0)
//   [B*D+B*T, end)       coverage (cov[b,t] = t)

__device__ float4 g_partial[BB * NCHUNK * D4];   // 2 MB scratch
__device__ unsigned int g_count[BB];             // zero-init; restored to 0 each run

__global__ __launch_bounds__(D4) void fused_kernel(const float4* __restrict__ vals,
                                                   float* __restrict__ out) {
    const int c   = blockIdx.x;      // 0..15 chunk
    const int b   = blockIdx.y;      // 0..31 batch
    const int tid = threadIdx.x;     // 0..255 (one float4 column)

    // ---- Stage 1: contiguous 256KB region per block (the 6 TB/s layout) ----
    const float4* __restrict__ p = vals + ((size_t)b * TT + (size_t)c * TC) * D4 + tid;
    float x = 0.f, y = 0.f, z = 0.f, w = 0.f;
#pragma unroll 16
    for (int t = 0; t < TC; ++t) {
        float4 v = p[(size_t)t * D4];
        x += v.x; y += v.y; z += v.z; w += v.w;
    }
    g_partial[(b * NCHUNK + c) * D4 + tid] = make_float4(x, y, z, w);

    // ---- Epilogue writes: 512 blocks x 16 float4 of aw and of cov ----
    const int blk = b * NCHUNK + c;  // 0..511
    if (tid < 16) {
        float4* aw4 = reinterpret_cast<float4*>(out + BB * DD);
        aw4[blk * 16 + tid] = make_float4(1.f, 1.f, 1.f, 1.f);
    } else if (tid >= 32 && tid < 48) {
        float4* cov4 = reinterpret_cast<float4*>(out + BB * DD + BB * TT);
        const int q = blk * 16 + (tid - 32);     // float4 index into [B,T]
        const int t0 = (q * 4) & (TT - 1);       // t of first element
        cov4[q] = make_float4((float)t0, (float)(t0 + 1), (float)(t0 + 2), (float)(t0 + 3));
    }

    // ---- Last-block-done reduction for this batch ----
    __threadfence();                 // make this block's partial globally visible
    __shared__ bool is_last;
    __syncthreads();                 // all partial writes (and fences) done
    if (tid == 0) {
        unsigned int prev = atomicAdd(&g_count[b], 1u);
        is_last = (prev == NCHUNK - 1);
    }
    __syncthreads();

    if (is_last) {
        __threadfence();             // acquire side of the fence pattern
        float X = 0.f, Y = 0.f, Z = 0.f, W = 0.f;
#pragma unroll
        for (int cc = 0; cc < NCHUNK; ++cc) {    // fixed order -> deterministic
            float4 v = g_partial[(b * NCHUNK + cc) * D4 + tid];
            X += v.x; Y += v.y; Z += v.z; W += v.w;
        }
        reinterpret_cast<float4*>(out)[(size_t)b * D4 + tid] = make_float4(X, Y, Z, W);
        if (tid == 0) g_count[b] = 0;            // reset for next graph replay
    }
}

extern "C" void kernel_launch(void* const* d_in, const int* in_sizes, int n_in,
                              void* d_out, int out_size) {
    // Inputs: query, values, W1, b1, W2, b2, W3, b3, V, bV
    const float4* values = (const float4*)d_in[1];
    float* out = (float*)d_out;

    dim3 grid(NCHUNK, BB);           // 512 blocks, all resident in one wave
    fused_kernel<<<grid, D4>>>(values, out);
}